// round 11
// baseline (speedup 1.0000x reference)
#include <cuda_runtime.h>
#include <cuda_bf16.h>
#include <math.h>
#include <stdint.h>

#define HID 128
#define DI 2048
#define DT 768
#define KTOT 2816
#define TSUP 1024
#define TQRY 16384
#define NTOK 17408
#define BK 64
#define NCH 44   /* 2816 / 64 */
#define STAGE 65536   /* per-stage: Ahi 16K, Alo 16K, Whi 16K, Wlo 16K */

// Scratch (static __device__ per allocation rules)
__device__ float g_C[NTOK * HID];     // LN1'd features
__device__ float g_QF[TQRY * HID];
__device__ float g_SF[TSUP * HID];
__device__ __nv_bfloat16 g_Whi[HID * KTOT];
__device__ __nv_bfloat16 g_Wlo[HID * KTOT];
__device__ __nv_bfloat16 g_Wvhi[HID * HID];
__device__ __nv_bfloat16 g_Wvlo[HID * HID];
__device__ __nv_bfloat16 g_Wohi[HID * HID];
__device__ __nv_bfloat16 g_Wolo[HID * HID];

// ---------------------------------------------------------------------------
// helpers
// ---------------------------------------------------------------------------
__device__ __forceinline__ uint32_t smem_u32_of(const void* p) {
    uint32_t a;
    asm("{ .reg .u64 t; cvta.to.shared.u64 t, %1; cvt.u32.u64 %0, t; }"
        : "=r"(a) : "l"(p));
    return a;
}
static __device__ __forceinline__ uint32_t sw128(uint32_t off) {
    return off ^ ((off >> 3) & 0x70);
}
__device__ __forceinline__ void ldsm4(uint32_t* r, uint32_t addr) {
    asm volatile("ldmatrix.sync.aligned.m8n8.x4.shared.b16 {%0,%1,%2,%3}, [%4];"
                 : "=r"(r[0]), "=r"(r[1]), "=r"(r[2]), "=r"(r[3]) : "r"(addr));
}
__device__ __forceinline__ void mma16816(float* c, const uint32_t* a, const uint32_t* b) {
    asm volatile(
        "mma.sync.aligned.m16n8k16.row.col.f32.bf16.bf16.f32 "
        "{%0,%1,%2,%3}, {%4,%5,%6,%7}, {%8,%9}, {%0,%1,%2,%3};"
        : "+f"(c[0]), "+f"(c[1]), "+f"(c[2]), "+f"(c[3])
        : "r"(a[0]), "r"(a[1]), "r"(a[2]), "r"(a[3]), "r"(b[0]), "r"(b[1]));
}
__device__ __forceinline__ void cp16(uint32_t dst, const void* src) {
    asm volatile("cp.async.cg.shared.global [%0], [%1], 16;"
                 :: "r"(dst), "l"(src) : "memory");
}
#define CP_COMMIT() asm volatile("cp.async.commit_group;" ::: "memory")
#define CP_WAIT0()  asm volatile("cp.async.wait_group 0;" ::: "memory")
#define CP_WAIT1()  asm volatile("cp.async.wait_group 1;" ::: "memory")

__device__ __forceinline__ void split2(float x, float y, uint32_t& hi, uint32_t& lo) {
    __nv_bfloat162 h = __float22bfloat162_rn(make_float2(x, y));
    float2 hf = __bfloat1622float2(h);
    __nv_bfloat162 l = __float22bfloat162_rn(make_float2(x - hf.x, y - hf.y));
    hi = *(uint32_t*)&h;
    lo = *(uint32_t*)&l;
}

// ---------------------------------------------------------------------------
// 16-warp fragment map + 32x32-tile compute (kept for k_query_fused)
// ---------------------------------------------------------------------------
struct Frag16 {
    uint32_t abase[2], aswz[2], bbase[2], bswz[2];
};
__device__ __forceinline__ void make_frag16(Frag16& fm, int lane, int mw, int nw) {
    #pragma unroll
    for (int mt = 0; mt < 2; ++mt) {
        uint32_t rb = (uint32_t)(mw * 32 + mt * 16 + (lane & 15)) * 128 + (lane >> 4) * 16;
        fm.abase[mt] = rb; fm.aswz[mt] = (rb >> 3) & 0x70;
    }
    #pragma unroll
    for (int p = 0; p < 2; ++p) {
        uint32_t rb = (uint32_t)(nw * 32 + p * 16 + ((lane >> 4) & 1) * 8 + (lane & 7)) * 128
                    + ((lane >> 3) & 1) * 16;
        fm.bbase[p] = rb; fm.bswz[p] = (rb >> 3) & 0x70;
    }
}
__device__ __forceinline__ void compute_c16(
    uint32_t AHI, uint32_t ALO, uint32_t WHI, uint32_t WLO,
    const Frag16& fm, float (*acc)[4][4])
{
    #pragma unroll
    for (int ks = 0; ks < 4; ++ks) {
        uint32_t ahi[2][4], alo[2][4];
        #pragma unroll
        for (int mt = 0; mt < 2; ++mt) {
            uint32_t o = (fm.abase[mt] + ks * 32) ^ fm.aswz[mt];
            ldsm4(ahi[mt], AHI + o);
            ldsm4(alo[mt], ALO + o);
        }
        uint32_t bhi[2][4], blo[2][4];
        #pragma unroll
        for (int p = 0; p < 2; ++p) {
            uint32_t o = (fm.bbase[p] + ks * 32) ^ fm.bswz[p];
            ldsm4(bhi[p], WHI + o);
            ldsm4(blo[p], WLO + o);
        }
        #pragma unroll
        for (int mt = 0; mt < 2; ++mt)
            #pragma unroll
            for (int j = 0; j < 4; ++j)
                mma16816(acc[mt][j], ahi[mt], &bhi[j >> 1][(j & 1) * 2]);
        #pragma unroll
        for (int mt = 0; mt < 2; ++mt)
            #pragma unroll
            for (int j = 0; j < 4; ++j)
                mma16816(acc[mt][j], ahi[mt], &blo[j >> 1][(j & 1) * 2]);
        #pragma unroll
        for (int mt = 0; mt < 2; ++mt)
            #pragma unroll
            for (int j = 0; j < 4; ++j)
                mma16816(acc[mt][j], alo[mt], &bhi[j >> 1][(j & 1) * 2]);
    }
}

// ---------------------------------------------------------------------------
// 8-warp fragment machinery for the input kernel: warp tile 64x32,
// explicit fragment DOUBLE BUFFERING so ldsm(ks+1) overlaps MMAs(ks).
// ---------------------------------------------------------------------------
struct Frag8 {
    uint32_t abase[4], aswz[4], bbase[2], bswz[2];
};
__device__ __forceinline__ void make_frag8(Frag8& fm, int lane, int mw, int nw) {
    #pragma unroll
    for (int mt = 0; mt < 4; ++mt) {
        uint32_t rb = (uint32_t)(mw * 64 + mt * 16 + (lane & 15)) * 128 + (lane >> 4) * 16;
        fm.abase[mt] = rb; fm.aswz[mt] = (rb >> 3) & 0x70;
    }
    #pragma unroll
    for (int p = 0; p < 2; ++p) {
        uint32_t rb = (uint32_t)(nw * 32 + p * 16 + ((lane >> 4) & 1) * 8 + (lane & 7)) * 128
                    + ((lane >> 3) & 1) * 16;
        fm.bbase[p] = rb; fm.bswz[p] = (rb >> 3) & 0x70;
    }
}
struct FragBuf {
    uint32_t ahi[4][4], alo[4][4], bhi[2][4], blo[2][4];
};
__device__ __forceinline__ void load_frags(
    uint32_t AHI, uint32_t ALO, uint32_t WHI, uint32_t WLO,
    int ks, const Frag8& fm, FragBuf& F)
{
    #pragma unroll
    for (int p = 0; p < 2; ++p) {
        uint32_t o = (fm.bbase[p] + ks * 32) ^ fm.bswz[p];
        ldsm4(F.bhi[p], WHI + o);
        ldsm4(F.blo[p], WLO + o);
    }
    #pragma unroll
    for (int mt = 0; mt < 4; ++mt) {
        uint32_t o = (fm.abase[mt] + ks * 32) ^ fm.aswz[mt];
        ldsm4(F.ahi[mt], AHI + o);
        ldsm4(F.alo[mt], ALO + o);
    }
}
__device__ __forceinline__ void mma_all(const FragBuf& F, float (*acc)[4][4]) {
    #pragma unroll
    for (int mt = 0; mt < 4; ++mt)
        #pragma unroll
        for (int j = 0; j < 4; ++j)
            mma16816(acc[mt][j], F.ahi[mt], &F.bhi[j >> 1][(j & 1) * 2]);
    #pragma unroll
    for (int mt = 0; mt < 4; ++mt)
        #pragma unroll
        for (int j = 0; j < 4; ++j)
            mma16816(acc[mt][j], F.ahi[mt], &F.blo[j >> 1][(j & 1) * 2]);
    #pragma unroll
    for (int mt = 0; mt < 4; ++mt)
        #pragma unroll
        for (int j = 0; j < 4; ++j)
            mma16816(acc[mt][j], F.alo[mt], &F.bhi[j >> 1][(j & 1) * 2]);
}

// ---------------------------------------------------------------------------
// Weight preconvert kernels
// ---------------------------------------------------------------------------
__global__ void __launch_bounds__(256) k_wconv(const float* __restrict__ Wi,
                                               const float* __restrict__ Wt) {
    int f4 = blockIdx.x * 256 + threadIdx.x;
    if (f4 >= HID * KTOT / 4) return;
    int row = f4 / (KTOT / 4);
    int col = (f4 % (KTOT / 4)) * 4;
    float4 v;
    if (col < DI) v = *(const float4*)(Wi + (size_t)row * DI + col);
    else          v = *(const float4*)(Wt + (size_t)row * DT + (col - DI));
    uint2 uh, ul;
    split2(v.x, v.y, uh.x, ul.x);
    split2(v.z, v.w, uh.y, ul.y);
    *(uint2*)(g_Whi + (size_t)row * KTOT + col) = uh;
    *(uint2*)(g_Wlo + (size_t)row * KTOT + col) = ul;
}

__global__ void __launch_bounds__(256) k_wconv_h(const float* __restrict__ W,
                                                 __nv_bfloat16* __restrict__ hi,
                                                 __nv_bfloat16* __restrict__ lo) {
    int f4 = blockIdx.x * 256 + threadIdx.x;
    if (f4 >= HID * HID / 4) return;
    float4 v = *(const float4*)(W + (size_t)f4 * 4);
    uint2 uh, ul;
    split2(v.x, v.y, uh.x, ul.x);
    split2(v.z, v.w, uh.y, ul.y);
    *(uint2*)(hi + (size_t)f4 * 4) = uh;
    *(uint2*)(lo + (size_t)f4 * 4) = ul;
}

// ---------------------------------------------------------------------------
// Input projection (HMMA bf16x3) + fused LN1, 8-warp CTA, 64x32 warp tiles,
// 3-stage smem pipeline + fragment double buffering:
// g_C = LN1(img@Wi.T + txt@Wt.T + bi + bt)
// ---------------------------------------------------------------------------
__global__ void __launch_bounds__(256) k_input_gemm_mma(
    const float* __restrict__ s_img, const float* __restrict__ s_txt,
    const float* __restrict__ q_img, const float* __restrict__ q_txt,
    const float* __restrict__ bi, const float* __restrict__ bt,
    const float* __restrict__ g1, const float* __restrict__ b1)
{
    extern __shared__ char smem[];
    const uint32_t sb = smem_u32_of(smem);
    float* bsum = (float*)smem;
    const uint32_t BASE = sb + 2048;

    const int tid = threadIdx.x, lane = tid & 31, wid = tid >> 5;
    const int mw = wid & 1, nw = wid >> 1;   // mw 0..1 (64-row halves), nw 0..3
    const int tokbase = blockIdx.x * 128;

    const float* img; const float* txt;
    if (tokbase < TSUP) {
        img = s_img + (size_t)tokbase * DI;
        txt = s_txt + (size_t)tokbase * DT;
    } else {
        img = q_img + (size_t)(tokbase - TSUP) * DI;
        txt = q_txt + (size_t)(tokbase - TSUP) * DT;
    }
    if (tid < HID) bsum[tid] = bi[tid] + bt[tid];

    const int row = tid >> 1;          // 0..127 (A/W staging row)
    const int ch  = (tid & 1) * 32;    // 32-col half of BK=64

    Frag8 fm;
    make_frag8(fm, lane, mw, nw);

    float acc[4][4][4];
    #pragma unroll
    for (int mt = 0; mt < 4; ++mt)
        #pragma unroll
        for (int j = 0; j < 4; ++j)
            #pragma unroll
            for (int q = 0; q < 4; ++q) acc[mt][j][q] = 0.0f;

    float4 areg[8];
    auto loadA = [&](int c) {
        int kg = c * BK;
        const float4* ap;
        if (kg < DI) ap = (const float4*)(img + (size_t)row * DI + kg + ch);
        else         ap = (const float4*)(txt + (size_t)row * DT + (kg - DI) + ch);
        #pragma unroll
        for (int i = 0; i < 8; ++i) areg[i] = ap[i];
    };
    auto storeA = [&](uint32_t buf) {
        char* pAhi = smem + (buf - sb);
        char* pAlo = pAhi + 16384;
        #pragma unroll
        for (int i = 0; i < 8; ++i) {
            float4 f = areg[i];
            uint2 uh, ul;
            split2(f.x, f.y, uh.x, ul.x);
            split2(f.z, f.w, uh.y, ul.y);
            uint32_t off = sw128((uint32_t)(row * 128 + (ch + i * 4) * 2));
            *(uint2*)(pAhi + off) = uh;
            *(uint2*)(pAlo + off) = ul;
        }
    };
    auto loadW = [&](int c, uint32_t buf) {
        int kg = c * BK;
        const __nv_bfloat16* sh = g_Whi + (size_t)row * KTOT + kg + ch;
        const __nv_bfloat16* sl = g_Wlo + (size_t)row * KTOT + kg + ch;
        #pragma unroll
        for (int i = 0; i < 4; ++i) {
            uint32_t off = sw128((uint32_t)(row * 128 + (ch + i * 8) * 2));
            cp16(buf + 32768 + off, sh + i * 8);
            cp16(buf + 49152 + off, sl + i * 8);
        }
    };

    // ---- prologue: stages 0,1 filled; areg = A(2) ----
    loadA(0); storeA(BASE + 0 * STAGE); loadW(0, BASE + 0 * STAGE); CP_COMMIT();
    loadA(1); storeA(BASE + 1 * STAGE); loadW(1, BASE + 1 * STAGE); CP_COMMIT();
    loadA(2);

    FragBuf F0, F1;

    // ---- main loop: ONE barrier per chunk; fragments double-buffered ----
    for (int c = 0; c < NCH; ++c) {
        if (c + 1 < NCH) CP_WAIT1(); else CP_WAIT0();   // W(c) arrived
        __syncthreads();   // STS of stage c visible; stage (c+2)%3 free
        if (c + 2 < NCH) {
            uint32_t nbuf = BASE + (uint32_t)((c + 2) % 3) * STAGE;
            storeA(nbuf);              // areg holds A(c+2)
            loadW(c + 2, nbuf);
            CP_COMMIT();
            if (c + 3 < NCH) loadA(c + 3);
        }
        const uint32_t cur = BASE + (uint32_t)(c % 3) * STAGE;
        const uint32_t AHI = cur, ALO = cur + 16384;
        const uint32_t WHI = cur + 32768, WLO = cur + 49152;
        // fragment-pipelined ks loop: ldsm(ks+1) issued before MMAs(ks)
        load_frags(AHI, ALO, WHI, WLO, 0, fm, F0);
        load_frags(AHI, ALO, WHI, WLO, 1, fm, F1);
        mma_all(F0, acc);
        load_frags(AHI, ALO, WHI, WLO, 2, fm, F0);
        mma_all(F1, acc);
        load_frags(AHI, ALO, WHI, WLO, 3, fm, F1);
        mma_all(F0, acc);
        mma_all(F1, acc);
    }

    // ---- epilogue: acc + bias -> smem scratch, LN1, -> g_C ----
    __syncthreads();
    float* Vs = (float*)(smem + 2048);   // [128][128] fp32 = 64KB
    {
        const int g = lane >> 2, t = lane & 3;
        #pragma unroll
        for (int mt = 0; mt < 4; ++mt) {
            int r0 = mw * 64 + mt * 16 + g;
            #pragma unroll
            for (int j = 0; j < 4; ++j) {
                int col = nw * 32 + j * 8 + t * 2;
                float b0 = bsum[col], b1v = bsum[col + 1];
                *(float2*)&Vs[r0 * 128 + col] =
                    make_float2(acc[mt][j][0] + b0, acc[mt][j][1] + b1v);
                *(float2*)&Vs[(r0 + 8) * 128 + col] =
                    make_float2(acc[mt][j][2] + b0, acc[mt][j][3] + b1v);
            }
        }
    }
    __syncthreads();
    {
        float4 gg = ((const float4*)g1)[lane];
        float4 bb = ((const float4*)b1)[lane];
        for (int tt = wid * 16; tt < wid * 16 + 16; ++tt) {
            float4 x = ((const float4*)&Vs[tt * 128])[lane];
            float s = x.x + x.y + x.z + x.w;
            #pragma unroll
            for (int o = 16; o > 0; o >>= 1) s += __shfl_xor_sync(0xffffffffu, s, o);
            float mean = s * (1.0f / 128.0f);
            float d0 = x.x - mean, d1 = x.y - mean, d2 = x.z - mean, d3 = x.w - mean;
            float v = d0*d0 + d1*d1 + d2*d2 + d3*d3;
            #pragma unroll
            for (int o = 16; o > 0; o >>= 1) v += __shfl_xor_sync(0xffffffffu, v, o);
            float inv = rsqrtf(v * (1.0f / 128.0f) + 1e-5f);
            float4 y;
            y.x = d0 * inv * gg.x + bb.x;
            y.y = d1 * inv * gg.y + bb.y;
            y.z = d2 * inv * gg.z + bb.z;
            y.w = d3 * inv * gg.w + bb.w;
            ((float4*)&g_C[(size_t)(tokbase + tt) * HID])[lane] = y;
        }
    }
}

// ---------------------------------------------------------------------------
// Fused query chain (HMMA bf16x3), 16-warp version (round-10, unchanged):
// QF = LN2(C@Wv.T + bv) @ Wo.T + bo, one block per 128 query tokens.
// ---------------------------------------------------------------------------
__global__ void __launch_bounds__(512) k_query_fused(
    const float* __restrict__ C,
    const float* __restrict__ bv, const float* __restrict__ g2,
    const float* __restrict__ b2, const float* __restrict__ bo)
{
    extern __shared__ char smem[];
    const uint32_t sb = smem_u32_of(smem);
    const uint32_t QA = sb + 2048;
    const uint32_t WV = QA + 65536;
    const uint32_t WO = WV + 65536;

    const int tid = threadIdx.x, lane = tid & 31, wid = tid >> 5;
    const int mw = wid & 3, nw = wid >> 2;
    const int tokbase = blockIdx.x * 128;
    const float* A = C + (size_t)tokbase * HID;

    Frag16 fm;
    make_frag16(fm, lane, mw, nw);

    const int row = tid >> 2;
    const int chunk = (tid >> 1) & 1;
    const int ch = (tid & 1) * 32;

    {
        const float4* ap = (const float4*)(A + (size_t)row * HID + chunk * BK + ch);
        char* pAhi = smem + 2048 + chunk * 32768;
        char* pAlo = pAhi + 16384;
        #pragma unroll
        for (int i = 0; i < 8; ++i) {
            float4 f = ap[i];
            uint2 uh, ul;
            split2(f.x, f.y, uh.x, ul.x);
            split2(f.z, f.w, uh.y, ul.y);
            uint32_t off = sw128((uint32_t)(row * 128 + (ch + i * 4) * 2));
            *(uint2*)(pAhi + off) = uh;
            *(uint2*)(pAlo + off) = ul;
        }
        const __nv_bfloat16* vh = g_Wvhi + (size_t)row * HID + chunk * BK + ch;
        const __nv_bfloat16* vl = g_Wvlo + (size_t)row * HID + chunk * BK + ch;
        const __nv_bfloat16* oh = g_Wohi + (size_t)row * HID + chunk * BK + ch;
        const __nv_bfloat16* ol = g_Wolo + (size_t)row * HID + chunk * BK + ch;
        #pragma unroll
        for (int i = 0; i < 4; ++i) {
            uint32_t off = sw128((uint32_t)(row * 128 + (ch + i * 8) * 2));
            cp16(WV + chunk * 32768 + off, vh + i * 8);
            cp16(WV + chunk * 32768 + 16384 + off, vl + i * 8);
            cp16(WO + chunk * 32768 + off, oh + i * 8);
            cp16(WO + chunk * 32768 + 16384 + off, ol + i * 8);
        }
    }
    CP_COMMIT();
    CP_WAIT0();
    __syncthreads();

    float acc[2][4][4];
    #pragma unroll
    for (int mt = 0; mt < 2; ++mt)
        #pragma unroll
        for (int j = 0; j < 4; ++j)
            #pragma unroll
            for (int q = 0; q < 4; ++q) acc[mt][j][q] = 0.0f;

    #pragma unroll
    for (int c = 0; c < 2; ++c)
        compute_c16(QA + c * 32768, QA + c * 32768 + 16384,
                    WV + c * 32768, WV + c * 32768 + 16384, fm, acc);
    __syncthreads();

    float* Vs = (float*)(smem + 2048);
    {
        const int g = lane >> 2, t = lane & 3;
        #pragma unroll
        for (int mt = 0; mt < 2; ++mt) {
            int r0 = mw * 32 + mt * 16 + g;
            #pragma unroll
            for (int j = 0; j < 4; ++j) {
                int col = nw * 32 + j * 8 + t * 2;
                float b0 = bv[col], b1v = bv[col + 1];
                *(float2*)&Vs[r0 * 128 + col] =
                    make_float2(acc[mt][j][0] + b0, acc[mt][j][1] + b1v);
                *(float2*)&Vs[(r0 + 8) * 128 + col] =
                    make_float2(acc[mt][j][2] + b0, acc[mt][j][3] + b1v);
            }
        }
    }
    __syncthreads();

    {
        float4 gg = ((const float4*)g2)[lane];
        float4 bb = ((const float4*)b2)[lane];
        const int cch = lane >> 4;
        char* pNhi = smem + 2048 + 65536 + cch * 32768;
        char* pNlo = pNhi + 16384;
        const int lc = (lane * 4) & 63;
        for (int tt = wid * 8; tt < wid * 8 + 8; ++tt) {
            float4 x = ((const float4*)&Vs[tt * 128])[lane];
            float s = x.x + x.y + x.z + x.w;
            #pragma unroll
            for (int o = 16; o > 0; o >>= 1) s += __shfl_xor_sync(0xffffffffu, s, o);
            float mean = s * (1.0f / 128.0f);
            float d0 = x.x - mean, d1 = x.y - mean, d2 = x.z - mean, d3 = x.w - mean;
            float v = d0*d0 + d1*d1 + d2*d2 + d3*d3;
            #pragma unroll
            for (int o = 16; o > 0; o >>= 1) v += __shfl_xor_sync(0xffffffffu, v, o);
            float inv = rsqrtf(v * (1.0f / 128.0f) + 1e-5f);
            float y0 = d0 * inv * gg.x + bb.x;
            float y1 = d1 * inv * gg.y + bb.y;
            float y2 = d2 * inv * gg.z + bb.z;
            float y3 = d3 * inv * gg.w + bb.w;
            uint2 uh, ul;
            split2(y0, y1, uh.x, ul.x);
            split2(y2, y3, uh.y, ul.y);
            uint32_t off = sw128((uint32_t)(tt * 128 + lc * 2));
            *(uint2*)(pNhi + off) = uh;
            *(uint2*)(pNlo + off) = ul;
        }
    }
    __syncthreads();

    #pragma unroll
    for (int mt = 0; mt < 2; ++mt)
        #pragma unroll
        for (int j = 0; j < 4; ++j)
            #pragma unroll
            for (int q = 0; q < 4; ++q) acc[mt][j][q] = 0.0f;
    #pragma unroll
    for (int c = 0; c < 2; ++c)
        compute_c16(WV + c * 32768, WV + c * 32768 + 16384,
                    WO + c * 32768, WO + c * 32768 + 16384, fm, acc);

    {
        const int g = lane >> 2, t = lane & 3;
        #pragma unroll
        for (int mt = 0; mt < 2; ++mt) {
            int r0 = tokbase + mw * 32 + mt * 16 + g;
            #pragma unroll
            for (int j = 0; j < 4; ++j) {
                int col = nw * 32 + j * 8 + t * 2;
                float b0 = bo[col], b1v = bo[col + 1];
                *(float2*)&g_QF[(size_t)r0 * HID + col] =
                    make_float2(acc[mt][j][0] + b0, acc[mt][j][1] + b1v);
                *(float2*)&g_QF[(size_t)(r0 + 8) * HID + col] =
                    make_float2(acc[mt][j][2] + b0, acc[mt][j][3] + b1v);
            }
        }
    }
}

// ---------------------------------------------------------------------------
// Support attention: one block per task t, 4 tokens
// ---------------------------------------------------------------------------
__global__ void __launch_bounds__(128) k_support_attn(
    const float* __restrict__ C,
    const float* __restrict__ Wq, const float* __restrict__ bq,
    const float* __restrict__ Wk, const float* __restrict__ bk,
    const float* __restrict__ Wv, const float* __restrict__ bv,
    const float* __restrict__ g2, const float* __restrict__ b2,
    const float* __restrict__ Wo, const float* __restrict__ bo,
    float* __restrict__ SF)
{
    __shared__ float cs[4][HID], qs[4][HID], ks[4][HID], vs[4][HID];
    __shared__ float am[4][4];
    __shared__ float cx[4][HID];
    int t = blockIdx.x;
    int j = threadIdx.x;
    const float* base = C + (size_t)t * 4 * HID;
    #pragma unroll
    for (int s = 0; s < 4; ++s) cs[s][j] = base[s * HID + j];
    __syncthreads();
    {
        float aq[4] = {0,0,0,0}, ak[4] = {0,0,0,0}, av[4] = {0,0,0,0};
        const float4* wq = (const float4*)(Wq + (size_t)j * HID);
        const float4* wk = (const float4*)(Wk + (size_t)j * HID);
        const float4* wv = (const float4*)(Wv + (size_t)j * HID);
        #pragma unroll 4
        for (int d4 = 0; d4 < 32; ++d4) {
            float4 q4 = wq[d4], k4 = wk[d4], v4 = wv[d4];
            #pragma unroll
            for (int s = 0; s < 4; ++s) {
                float c0 = cs[s][d4*4+0], c1 = cs[s][d4*4+1];
                float c2 = cs[s][d4*4+2], c3 = cs[s][d4*4+3];
                aq[s] += q4.x*c0 + q4.y*c1 + q4.z*c2 + q4.w*c3;
                ak[s] += k4.x*c0 + k4.y*c1 + k4.z*c2 + k4.w*c3;
                av[s] += v4.x*c0 + v4.y*c1 + v4.z*c2 + v4.w*c3;
            }
        }
        #pragma unroll
        for (int s = 0; s < 4; ++s) {
            qs[s][j] = aq[s] + bq[j];
            ks[s][j] = ak[s] + bk[j];
            vs[s][j] = av[s] + bv[j];
        }
    }
    __syncthreads();
    if (j < 16) {
        int s = j >> 2, s2 = j & 3;
        float d = 0.0f;
        for (int dd = 0; dd < HID; ++dd) d += qs[s][dd] * ks[s2][dd];
        am[s][s2] = d * (1.0f / (sqrtf(128.0f) + 1e-8f));
    }
    __syncthreads();
    if (j < 4) {
        float r[4];
        float mx = -1e30f;
        #pragma unroll
        for (int c = 0; c < 4; ++c) { r[c] = am[j][c]; mx = fmaxf(mx, r[c]); }
        float sum = 0.0f;
        #pragma unroll
        for (int c = 0; c < 4; ++c) { r[c] = expf(r[c] - mx); sum += r[c]; }
        #pragma unroll
        for (int c = 0; c < 4; ++c) r[c] /= sum;
        float sum2 = 0.0f;
        #pragma unroll
        for (int c = 0; c < 4; ++c) { r[c] += 1e-10f; sum2 += r[c]; }
        #pragma unroll
        for (int c = 0; c < 4; ++c) {
            r[c] /= sum2;
            am[j][c] = fminf(fmaxf(r[c], 1e-7f), 1.0f);
        }
    }
    __syncthreads();
    #pragma unroll
    for (int s = 0; s < 4; ++s) {
        float v = 0.0f;
        #pragma unroll
        for (int s2 = 0; s2 < 4; ++s2) v += am[s][s2] * vs[s2][j];
        cx[s][j] = v;
    }
    __syncthreads();
    {
        int w = j >> 5, lane = j & 31;
        float x0 = cx[w][lane], x1 = cx[w][lane+32], x2 = cx[w][lane+64], x3 = cx[w][lane+96];
        float s = x0 + x1 + x2 + x3;
        #pragma unroll
        for (int o = 16; o > 0; o >>= 1) s += __shfl_xor_sync(0xffffffffu, s, o);
        float mean = s * (1.0f / 128.0f);
        float d0 = x0 - mean, d1 = x1 - mean, d2 = x2 - mean, d3 = x3 - mean;
        float v = d0*d0 + d1*d1 + d2*d2 + d3*d3;
        #pragma unroll
        for (int o = 16; o > 0; o >>= 1) v += __shfl_xor_sync(0xffffffffu, v, o);
        float inv = rsqrtf(v * (1.0f / 128.0f) + 1e-5f);
        cx[w][lane]    = d0 * inv * g2[lane]    + b2[lane];
        cx[w][lane+32] = d1 * inv * g2[lane+32] + b2[lane+32];
        cx[w][lane+64] = d2 * inv * g2[lane+64] + b2[lane+64];
        cx[w][lane+96] = d3 * inv * g2[lane+96] + b2[lane+96];
    }
    __syncthreads();
    {
        const float4* wo = (const float4*)(Wo + (size_t)j * HID);
        float ao[4] = {0,0,0,0};
        #pragma unroll 4
        for (int d4 = 0; d4 < 32; ++d4) {
            float4 w4 = wo[d4];
            #pragma unroll
            for (int s = 0; s < 4; ++s) {
                ao[s] += w4.x * cx[s][d4*4+0] + w4.y * cx[s][d4*4+1]
                       + w4.z * cx[s][d4*4+2] + w4.w * cx[s][d4*4+3];
            }
        }
        #pragma unroll
        for (int s = 0; s < 4; ++s)
            SF[(size_t)(t*4 + s) * HID + j] = ao[s] + bo[j];
    }
}

// ---------------------------------------------------------------------------
// Cosine logits: one block per task
// ---------------------------------------------------------------------------
__global__ void __launch_bounds__(128) k_logits(
    const float* __restrict__ QF, const float* __restrict__ SF,
    float* __restrict__ out)
{
    __shared__ float pn[4][HID];
    int t = blockIdx.x;
    int w = threadIdx.x >> 5, lane = threadIdx.x & 31;
    {
        const float4* row = (const float4*)(SF + (size_t)(t*4 + w) * HID);
        float4 x = row[lane];
        float n2 = x.x*x.x + x.y*x.y + x.z*x.z + x.w*x.w;
        #pragma unroll
        for (int o = 16; o > 0; o >>= 1) n2 += __shfl_xor_sync(0xffffffffu, n2, o);
        float inv = 1.0f / fmaxf(sqrtf(n2), 1e-8f);
        float4 y;
        y.x = x.x * inv; y.y = x.y * inv; y.z = x.z * inv; y.w = x.w * inv;
        ((float4*)pn[w])[lane] = y;
    }
    __syncthreads();
    for (int q = w; q < 64; q += 4) {
        const float4* row = (const float4*)(QF + (size_t)(t*64 + q) * HID);
        float4 x = row[lane];
        float n2 = x.x*x.x + x.y*x.y + x.z*x.z + x.w*x.w;
        float d[4];
        #pragma unroll
        for (int c = 0; c < 4; ++c) {
            float4 p = ((const float4*)pn[c])[lane];
            d[c] = x.x*p.x + x.y*p.y + x.z*p.z + x.w*p.w;
        }
        #pragma unroll
        for (int o = 16; o > 0; o >>= 1) {
            n2 += __shfl_xor_sync(0xffffffffu, n2, o);
            #pragma unroll
            for (int c = 0; c < 4; ++c)
                d[c] += __shfl_xor_sync(0xffffffffu, d[c], o);
        }
        if (lane == 0) {
            float inv = 10.0f / fmaxf(sqrtf(n2), 1e-8f);
            float4 r;
            r.x = d[0]*inv; r.y = d[1]*inv; r.z = d[2]*inv; r.w = d[3]*inv;
            ((float4*)(out + ((size_t)t*64 + q) * 4))[0] = r;
        }
    }
}

extern "C" void kernel_launch(void* const* d_in, const int* in_sizes, int n_in,
                              void* d_out, int out_size)
{
    const float* s_img = (const float*)d_in[0];
    const float* s_txt = (const float*)d_in[1];
    /* d_in[2] = support_labels (unused) */
    const float* q_img = (const float*)d_in[3];
    const float* q_txt = (const float*)d_in[4];
    const float* Wi = (const float*)d_in[5];
    const float* bi = (const float*)d_in[6];
    const float* Wt = (const float*)d_in[7];
    const float* bt = (const float*)d_in[8];
    const float* g1 = (const float*)d_in[9];
    const float* b1 = (const float*)d_in[10];
    const float* Wq = (const float*)d_in[11];
    const float* bq = (const float*)d_in[12];
    const float* Wk = (const float*)d_in[13];
    const float* bk = (const float*)d_in[14];
    const float* Wv = (const float*)d_in[15];
    const float* bv = (const float*)d_in[16];
    const float* g2 = (const float*)d_in[17];
    const float* b2 = (const float*)d_in[18];
    const float* Wo = (const float*)d_in[19];
    const float* bo = (const float*)d_in[20];

    float *pC, *pQF, *pSF;
    cudaGetSymbolAddress((void**)&pC, g_C);
    cudaGetSymbolAddress((void**)&pQF, g_QF);
    cudaGetSymbolAddress((void**)&pSF, g_SF);
    __nv_bfloat16 *pWvhi, *pWvlo, *pWohi, *pWolo;
    cudaGetSymbolAddress((void**)&pWvhi, g_Wvhi);
    cudaGetSymbolAddress((void**)&pWvlo, g_Wvlo);
    cudaGetSymbolAddress((void**)&pWohi, g_Wohi);
    cudaGetSymbolAddress((void**)&pWolo, g_Wolo);

    const int SMEM_IN = 2048 + 3 * STAGE;       // 198656
    const int SMEM_QF = 2048 + 3 * 65536;       // 198656
    static bool attr_set = false;
    if (!attr_set) {
        cudaFuncSetAttribute(k_input_gemm_mma,
                             cudaFuncAttributeMaxDynamicSharedMemorySize, SMEM_IN);
        cudaFuncSetAttribute(k_query_fused,
                             cudaFuncAttributeMaxDynamicSharedMemorySize, SMEM_QF);
        attr_set = true;
    }

    // 0) preconvert weights into bf16 hi/lo
    k_wconv<<<(HID * KTOT / 4 + 255) / 256, 256>>>(Wi, Wt);
    k_wconv_h<<<16, 256>>>(Wv, pWvhi, pWvlo);
    k_wconv_h<<<16, 256>>>(Wo, pWohi, pWolo);
    // 1) input projection + LN1 (HMMA bf16x3, 8 warps, 64x32 tiles,
    //    3-stage smem pipeline + fragment double buffering)
    k_input_gemm_mma<<<NTOK / 128, 256, SMEM_IN>>>(s_img, s_txt, q_img, q_txt,
                                                   bi, bt, g1, b1);
    // 2) fused query chain (16 warps): Wv GEMM -> LN2 -> Wo GEMM
    k_query_fused<<<TQRY / 128, 512, SMEM_QF>>>(pC + (size_t)TSUP * HID,
                                                bv, g2, b2, bo);
    // 3) support path: tiny full attention per task
    k_support_attn<<<256, 128>>>(pC, Wq, bq, Wk, bk, Wv, bv, g2, b2, Wo, bo, pSF);
    // 4) cosine logits
    k_logits<<<256, 128>>>(pQF, pSF, (float*)d_out);
}

// round 12
// speedup vs baseline: 1.0976x; 1.0976x over previous
#include <cuda_runtime.h>
#include <cuda_bf16.h>
#include <math.h>
#include <stdint.h>

#define HID 128
#define DI 2048
#define DT 768
#define KTOT 2816
#define TSUP 1024
#define TQRY 16384
#define NTOK 17408
#define BK 64
#define NCH 44   /* 2816 / 64 */
#define STAGE 65536   /* per-stage: Ahi 16K, Alo 16K, Whi 16K, Wlo 16K */

// Scratch (static __device__ per allocation rules)
__device__ float g_C[NTOK * HID];     // LN1'd features (support blocks only)
__device__ float g_QF[TQRY * HID];
__device__ float g_SF[TSUP * HID];
__device__ __nv_bfloat16 g_Whi[HID * KTOT];
__device__ __nv_bfloat16 g_Wlo[HID * KTOT];
__device__ __nv_bfloat16 g_Wvhi[HID * HID];
__device__ __nv_bfloat16 g_Wvlo[HID * HID];
__device__ __nv_bfloat16 g_Wohi[HID * HID];
__device__ __nv_bfloat16 g_Wolo[HID * HID];

// ---------------------------------------------------------------------------
// helpers
// ---------------------------------------------------------------------------
__device__ __forceinline__ uint32_t smem_u32_of(const void* p) {
    uint32_t a;
    asm("{ .reg .u64 t; cvta.to.shared.u64 t, %1; cvt.u32.u64 %0, t; }"
        : "=r"(a) : "l"(p));
    return a;
}
static __device__ __forceinline__ uint32_t sw128(uint32_t off) {
    return off ^ ((off >> 3) & 0x70);
}
__device__ __forceinline__ void ldsm4(uint32_t* r, uint32_t addr) {
    asm volatile("ldmatrix.sync.aligned.m8n8.x4.shared.b16 {%0,%1,%2,%3}, [%4];"
                 : "=r"(r[0]), "=r"(r[1]), "=r"(r[2]), "=r"(r[3]) : "r"(addr));
}
__device__ __forceinline__ void mma16816(float* c, const uint32_t* a, const uint32_t* b) {
    asm volatile(
        "mma.sync.aligned.m16n8k16.row.col.f32.bf16.bf16.f32 "
        "{%0,%1,%2,%3}, {%4,%5,%6,%7}, {%8,%9}, {%0,%1,%2,%3};"
        : "+f"(c[0]), "+f"(c[1]), "+f"(c[2]), "+f"(c[3])
        : "r"(a[0]), "r"(a[1]), "r"(a[2]), "r"(a[3]), "r"(b[0]), "r"(b[1]));
}
__device__ __forceinline__ void cp16(uint32_t dst, const void* src) {
    asm volatile("cp.async.cg.shared.global [%0], [%1], 16;"
                 :: "r"(dst), "l"(src) : "memory");
}
#define CP_COMMIT() asm volatile("cp.async.commit_group;" ::: "memory")
#define CP_WAIT0()  asm volatile("cp.async.wait_group 0;" ::: "memory")
#define CP_WAIT1()  asm volatile("cp.async.wait_group 1;" ::: "memory")

__device__ __forceinline__ void split2(float x, float y, uint32_t& hi, uint32_t& lo) {
    __nv_bfloat162 h = __float22bfloat162_rn(make_float2(x, y));
    float2 hf = __bfloat1622float2(h);
    __nv_bfloat162 l = __float22bfloat162_rn(make_float2(x - hf.x, y - hf.y));
    hi = *(uint32_t*)&h;
    lo = *(uint32_t*)&l;
}

// ---------------------------------------------------------------------------
// 16-warp fragment map + 32x32-tile bf16x3 compute over one 64-K chunk
// ---------------------------------------------------------------------------
struct Frag16 {
    uint32_t abase[2], aswz[2], bbase[2], bswz[2];
};
__device__ __forceinline__ void make_frag16(Frag16& fm, int lane, int mw, int nw) {
    #pragma unroll
    for (int mt = 0; mt < 2; ++mt) {
        uint32_t rb = (uint32_t)(mw * 32 + mt * 16 + (lane & 15)) * 128 + (lane >> 4) * 16;
        fm.abase[mt] = rb; fm.aswz[mt] = (rb >> 3) & 0x70;
    }
    #pragma unroll
    for (int p = 0; p < 2; ++p) {
        uint32_t rb = (uint32_t)(nw * 32 + p * 16 + ((lane >> 4) & 1) * 8 + (lane & 7)) * 128
                    + ((lane >> 3) & 1) * 16;
        fm.bbase[p] = rb; fm.bswz[p] = (rb >> 3) & 0x70;
    }
}
__device__ __forceinline__ void compute_c16(
    uint32_t AHI, uint32_t ALO, uint32_t WHI, uint32_t WLO,
    const Frag16& fm, float (*acc)[4][4])
{
    #pragma unroll
    for (int ks = 0; ks < 4; ++ks) {
        uint32_t ahi[2][4], alo[2][4];
        #pragma unroll
        for (int mt = 0; mt < 2; ++mt) {
            uint32_t o = (fm.abase[mt] + ks * 32) ^ fm.aswz[mt];
            ldsm4(ahi[mt], AHI + o);
            ldsm4(alo[mt], ALO + o);
        }
        uint32_t bhi[2][4], blo[2][4];
        #pragma unroll
        for (int p = 0; p < 2; ++p) {
            uint32_t o = (fm.bbase[p] + ks * 32) ^ fm.bswz[p];
            ldsm4(bhi[p], WHI + o);
            ldsm4(blo[p], WLO + o);
        }
        #pragma unroll
        for (int mt = 0; mt < 2; ++mt)
            #pragma unroll
            for (int j = 0; j < 4; ++j)
                mma16816(acc[mt][j], ahi[mt], &bhi[j >> 1][(j & 1) * 2]);
        #pragma unroll
        for (int mt = 0; mt < 2; ++mt)
            #pragma unroll
            for (int j = 0; j < 4; ++j)
                mma16816(acc[mt][j], ahi[mt], &blo[j >> 1][(j & 1) * 2]);
        #pragma unroll
        for (int mt = 0; mt < 2; ++mt)
            #pragma unroll
            for (int j = 0; j < 4; ++j)
                mma16816(acc[mt][j], alo[mt], &bhi[j >> 1][(j & 1) * 2]);
    }
}

// ---------------------------------------------------------------------------
// Weight preconvert kernels
// ---------------------------------------------------------------------------
__global__ void __launch_bounds__(256) k_wconv(const float* __restrict__ Wi,
                                               const float* __restrict__ Wt) {
    int f4 = blockIdx.x * 256 + threadIdx.x;
    if (f4 >= HID * KTOT / 4) return;
    int row = f4 / (KTOT / 4);
    int col = (f4 % (KTOT / 4)) * 4;
    float4 v;
    if (col < DI) v = *(const float4*)(Wi + (size_t)row * DI + col);
    else          v = *(const float4*)(Wt + (size_t)row * DT + (col - DI));
    uint2 uh, ul;
    split2(v.x, v.y, uh.x, ul.x);
    split2(v.z, v.w, uh.y, ul.y);
    *(uint2*)(g_Whi + (size_t)row * KTOT + col) = uh;
    *(uint2*)(g_Wlo + (size_t)row * KTOT + col) = ul;
}

__global__ void __launch_bounds__(256) k_wconv_h(const float* __restrict__ W,
                                                 __nv_bfloat16* __restrict__ hi,
                                                 __nv_bfloat16* __restrict__ lo) {
    int f4 = blockIdx.x * 256 + threadIdx.x;
    if (f4 >= HID * HID / 4) return;
    float4 v = *(const float4*)(W + (size_t)f4 * 4);
    uint2 uh, ul;
    split2(v.x, v.y, uh.x, ul.x);
    split2(v.z, v.w, uh.y, ul.y);
    *(uint2*)(hi + (size_t)f4 * 4) = uh;
    *(uint2*)(lo + (size_t)f4 * 4) = ul;
}

// ---------------------------------------------------------------------------
// MEGA KERNEL: input projection (HMMA bf16x3, 16 warps, 3-stage pipeline)
// + fused LN1, and for QUERY blocks the full chain:
//   QF = LN2(LN1(c) @ Wv.T + bv) @ Wo.T + bo    (no g_C round trip)
// Support blocks (tokbase < TSUP) write LN1(c) -> g_C and exit.
// ---------------------------------------------------------------------------
__global__ void __launch_bounds__(512) k_input_mega(
    const float* __restrict__ s_img, const float* __restrict__ s_txt,
    const float* __restrict__ q_img, const float* __restrict__ q_txt,
    const float* __restrict__ bi, const float* __restrict__ bt,
    const float* __restrict__ g1, const float* __restrict__ b1,
    const float* __restrict__ bv, const float* __restrict__ g2,
    const float* __restrict__ b2, const float* __restrict__ bo)
{
    extern __shared__ char smem[];
    const uint32_t sb = smem_u32_of(smem);
    float* bsum = (float*)smem;
    const uint32_t BASE = sb + 2048;

    const int tid = threadIdx.x, lane = tid & 31, wid = tid >> 5;
    const int mw = wid & 3, nw = wid >> 2;
    const int tokbase = blockIdx.x * 128;
    const bool isQuery = (tokbase >= TSUP);

    const float* img; const float* txt;
    if (!isQuery) {
        img = s_img + (size_t)tokbase * DI;
        txt = s_txt + (size_t)tokbase * DT;
    } else {
        img = q_img + (size_t)(tokbase - TSUP) * DI;
        txt = q_txt + (size_t)(tokbase - TSUP) * DT;
    }
    if (tid < HID) bsum[tid] = bi[tid] + bt[tid];

    const int row = tid >> 2;          // 0..127
    const int cq  = (tid & 3) * 16;    // 16-col quarter of BK=64

    Frag16 fm;
    make_frag16(fm, lane, mw, nw);

    float acc[2][4][4];
    #pragma unroll
    for (int mt = 0; mt < 2; ++mt)
        #pragma unroll
        for (int j = 0; j < 4; ++j)
            #pragma unroll
            for (int q = 0; q < 4; ++q) acc[mt][j][q] = 0.0f;

    float4 areg[4];
    auto loadA = [&](int c) {
        int kg = c * BK;
        const float4* ap;
        if (kg < DI) ap = (const float4*)(img + (size_t)row * DI + kg + cq);
        else         ap = (const float4*)(txt + (size_t)row * DT + (kg - DI) + cq);
        #pragma unroll
        for (int i = 0; i < 4; ++i) areg[i] = ap[i];
    };
    auto storeA = [&](uint32_t buf) {
        char* pAhi = smem + (buf - sb);
        char* pAlo = pAhi + 16384;
        #pragma unroll
        for (int i = 0; i < 4; ++i) {
            float4 f = areg[i];
            uint2 uh, ul;
            split2(f.x, f.y, uh.x, ul.x);
            split2(f.z, f.w, uh.y, ul.y);
            uint32_t off = sw128((uint32_t)(row * 128 + (cq + i * 4) * 2));
            *(uint2*)(pAhi + off) = uh;
            *(uint2*)(pAlo + off) = ul;
        }
    };
    auto loadW = [&](int c, uint32_t buf) {
        int kg = c * BK;
        const __nv_bfloat16* sh = g_Whi + (size_t)row * KTOT + kg + cq;
        const __nv_bfloat16* sl = g_Wlo + (size_t)row * KTOT + kg + cq;
        #pragma unroll
        for (int i = 0; i < 2; ++i) {
            uint32_t off = sw128((uint32_t)(row * 128 + (cq + i * 8) * 2));
            cp16(buf + 32768 + off, sh + i * 8);
            cp16(buf + 49152 + off, sl + i * 8);
        }
    };

    // ---- prologue: stages 0,1 filled; areg = A(2) ----
    loadA(0); storeA(BASE + 0 * STAGE); loadW(0, BASE + 0 * STAGE); CP_COMMIT();
    loadA(1); storeA(BASE + 1 * STAGE); loadW(1, BASE + 1 * STAGE); CP_COMMIT();
    loadA(2);

    // ---- main loop: ONE barrier per chunk ----
    for (int c = 0; c < NCH; ++c) {
        if (c + 1 < NCH) CP_WAIT1(); else CP_WAIT0();
        __syncthreads();
        if (c + 2 < NCH) {
            uint32_t nbuf = BASE + (uint32_t)((c + 2) % 3) * STAGE;
            storeA(nbuf);
            loadW(c + 2, nbuf);
            CP_COMMIT();
            if (c + 3 < NCH) loadA(c + 3);
        }
        uint32_t cur = BASE + (uint32_t)(c % 3) * STAGE;
        compute_c16(cur, cur + 16384, cur + 32768, cur + 49152, fm, acc);
    }

    // ---- epilogue ----
    __syncthreads();                       // (a) all stage reads done
    float* Vs = (float*)(smem + 2048);     // stage0: [128][128] fp32
    const uint32_t CN = BASE + 1 * STAGE;  // stage1: staged activations bf16
    const uint32_t WT = BASE + 2 * STAGE;  // stage2: staged weights bf16

    // staging split for weight tiles: row 0..127, chunk, 32-col half
    const int schunk = (tid >> 1) & 1;
    const int sch = (tid & 1) * 32;
    auto loadWpair = [&](const __nv_bfloat16* hi, const __nv_bfloat16* lo, uint32_t dst) {
        const __nv_bfloat16* h = hi + (size_t)row * HID + schunk * BK + sch;
        const __nv_bfloat16* l = lo + (size_t)row * HID + schunk * BK + sch;
        #pragma unroll
        for (int i = 0; i < 4; ++i) {
            uint32_t off = sw128((uint32_t)(row * 128 + (sch + i * 8) * 2));
            cp16(dst + schunk * 32768 + off, h + i * 8);
            cp16(dst + schunk * 32768 + 16384 + off, l + i * 8);
        }
    };
    if (isQuery) { loadWpair(g_Wvhi, g_Wvlo, WT); CP_COMMIT(); }

    // epi1: acc + (bi+bt) -> Vs
    {
        const int g = lane >> 2, t = lane & 3;
        #pragma unroll
        for (int mt = 0; mt < 2; ++mt) {
            int r0 = mw * 32 + mt * 16 + g;
            #pragma unroll
            for (int j = 0; j < 4; ++j) {
                int col = nw * 32 + j * 8 + t * 2;
                float b0 = bsum[col], b1v = bsum[col + 1];
                *(float2*)&Vs[r0 * 128 + col] =
                    make_float2(acc[mt][j][0] + b0, acc[mt][j][1] + b1v);
                *(float2*)&Vs[(r0 + 8) * 128 + col] =
                    make_float2(acc[mt][j][2] + b0, acc[mt][j][3] + b1v);
            }
        }
    }
    __syncthreads();                       // (b) Vs visible

    // LN over Vs; writer differs by block type
    const int cch = lane >> 4;             // 64-col chunk this lane covers
    const int lc  = (lane * 4) & 63;       // local col within chunk
    {
        float4 gg = ((const float4*)g1)[lane];
        float4 bb = ((const float4*)b1)[lane];
        char* pNhi = smem + 2048 + STAGE + cch * 32768;        // CN region
        char* pNlo = pNhi + 16384;
        for (int tt = wid * 8; tt < wid * 8 + 8; ++tt) {
            float4 x = ((const float4*)&Vs[tt * 128])[lane];
            float s = x.x + x.y + x.z + x.w;
            #pragma unroll
            for (int o = 16; o > 0; o >>= 1) s += __shfl_xor_sync(0xffffffffu, s, o);
            float mean = s * (1.0f / 128.0f);
            float d0 = x.x - mean, d1 = x.y - mean, d2 = x.z - mean, d3 = x.w - mean;
            float v = d0*d0 + d1*d1 + d2*d2 + d3*d3;
            #pragma unroll
            for (int o = 16; o > 0; o >>= 1) v += __shfl_xor_sync(0xffffffffu, v, o);
            float inv = rsqrtf(v * (1.0f / 128.0f) + 1e-5f);
            float y0 = d0 * inv * gg.x + bb.x;
            float y1 = d1 * inv * gg.y + bb.y;
            float y2 = d2 * inv * gg.z + bb.z;
            float y3 = d3 * inv * gg.w + bb.w;
            if (!isQuery) {
                float4 y = make_float4(y0, y1, y2, y3);
                ((float4*)&g_C[(size_t)(tokbase + tt) * HID])[lane] = y;
            } else {
                uint2 uh, ul;
                split2(y0, y1, uh.x, ul.x);
                split2(y2, y3, uh.y, ul.y);
                uint32_t off = sw128((uint32_t)(tt * 128 + lc * 2));
                *(uint2*)(pNhi + off) = uh;
                *(uint2*)(pNlo + off) = ul;
            }
        }
    }
    if (!isQuery) return;   // support blocks done

    CP_WAIT0();
    __syncthreads();                       // (c) CN + Wv tiles visible

    // GEMM1: V = CN @ Wv.T
    #pragma unroll
    for (int mt = 0; mt < 2; ++mt)
        #pragma unroll
        for (int j = 0; j < 4; ++j)
            #pragma unroll
            for (int q = 0; q < 4; ++q) acc[mt][j][q] = 0.0f;
    #pragma unroll
    for (int c = 0; c < 2; ++c)
        compute_c16(CN + c * 32768, CN + c * 32768 + 16384,
                    WT + c * 32768, WT + c * 32768 + 16384, fm, acc);
    __syncthreads();                       // (d) CN + WT reads done

    loadWpair(g_Wohi, g_Wolo, CN);         // Wo tiles overwrite CN region
    CP_COMMIT();

    // epi2: acc + bv -> Vs
    {
        const int g = lane >> 2, t = lane & 3;
        #pragma unroll
        for (int mt = 0; mt < 2; ++mt) {
            int r0 = mw * 32 + mt * 16 + g;
            #pragma unroll
            for (int j = 0; j < 4; ++j) {
                int col = nw * 32 + j * 8 + t * 2;
                float b0 = bv[col], b1v = bv[col + 1];
                *(float2*)&Vs[r0 * 128 + col] =
                    make_float2(acc[mt][j][0] + b0, acc[mt][j][1] + b1v);
                *(float2*)&Vs[(r0 + 8) * 128 + col] =
                    make_float2(acc[mt][j][2] + b0, acc[mt][j][3] + b1v);
            }
        }
    }
    __syncthreads();                       // (e) Vs visible

    // LN2: read Vs -> write Vn bf16 hi/lo into WT region
    {
        float4 gg = ((const float4*)g2)[lane];
        float4 bb = ((const float4*)b2)[lane];
        char* pNhi = smem + 2048 + 2 * STAGE + cch * 32768;    // WT region
        char* pNlo = pNhi + 16384;
        for (int tt = wid * 8; tt < wid * 8 + 8; ++tt) {
            float4 x = ((const float4*)&Vs[tt * 128])[lane];
            float s = x.x + x.y + x.z + x.w;
            #pragma unroll
            for (int o = 16; o > 0; o >>= 1) s += __shfl_xor_sync(0xffffffffu, s, o);
            float mean = s * (1.0f / 128.0f);
            float d0 = x.x - mean, d1 = x.y - mean, d2 = x.z - mean, d3 = x.w - mean;
            float v = d0*d0 + d1*d1 + d2*d2 + d3*d3;
            #pragma unroll
            for (int o = 16; o > 0; o >>= 1) v += __shfl_xor_sync(0xffffffffu, v, o);
            float inv = rsqrtf(v * (1.0f / 128.0f) + 1e-5f);
            float y0 = d0 * inv * gg.x + bb.x;
            float y1 = d1 * inv * gg.y + bb.y;
            float y2 = d2 * inv * gg.z + bb.z;
            float y3 = d3 * inv * gg.w + bb.w;
            uint2 uh, ul;
            split2(y0, y1, uh.x, ul.x);
            split2(y2, y3, uh.y, ul.y);
            uint32_t off = sw128((uint32_t)(tt * 128 + lc * 2));
            *(uint2*)(pNhi + off) = uh;
            *(uint2*)(pNlo + off) = ul;
        }
    }
    CP_WAIT0();
    __syncthreads();                       // (f) Vn + Wo tiles visible

    // GEMM2: QF = Vn @ Wo.T
    #pragma unroll
    for (int mt = 0; mt < 2; ++mt)
        #pragma unroll
        for (int j = 0; j < 4; ++j)
            #pragma unroll
            for (int q = 0; q < 4; ++q) acc[mt][j][q] = 0.0f;
    #pragma unroll
    for (int c = 0; c < 2; ++c)
        compute_c16(WT + c * 32768, WT + c * 32768 + 16384,
                    CN + c * 32768, CN + c * 32768 + 16384, fm, acc);

    // epi3: acc + bo -> g_QF
    {
        const int g = lane >> 2, t = lane & 3;
        const int qbase = tokbase - TSUP;
        #pragma unroll
        for (int mt = 0; mt < 2; ++mt) {
            int r0 = qbase + mw * 32 + mt * 16 + g;
            #pragma unroll
            for (int j = 0; j < 4; ++j) {
                int col = nw * 32 + j * 8 + t * 2;
                float b0 = bo[col], b1v = bo[col + 1];
                *(float2*)&g_QF[(size_t)r0 * HID + col] =
                    make_float2(acc[mt][j][0] + b0, acc[mt][j][1] + b1v);
                *(float2*)&g_QF[(size_t)(r0 + 8) * HID + col] =
                    make_float2(acc[mt][j][2] + b0, acc[mt][j][3] + b1v);
            }
        }
    }
}

// ---------------------------------------------------------------------------
// Support attention: one block per task t, 4 tokens
// ---------------------------------------------------------------------------
__global__ void __launch_bounds__(128) k_support_attn(
    const float* __restrict__ C,
    const float* __restrict__ Wq, const float* __restrict__ bq,
    const float* __restrict__ Wk, const float* __restrict__ bk,
    const float* __restrict__ Wv, const float* __restrict__ bv,
    const float* __restrict__ g2, const float* __restrict__ b2,
    const float* __restrict__ Wo, const float* __restrict__ bo,
    float* __restrict__ SF)
{
    __shared__ float cs[4][HID], qs[4][HID], ks[4][HID], vs[4][HID];
    __shared__ float am[4][4];
    __shared__ float cx[4][HID];
    int t = blockIdx.x;
    int j = threadIdx.x;
    const float* base = C + (size_t)t * 4 * HID;
    #pragma unroll
    for (int s = 0; s < 4; ++s) cs[s][j] = base[s * HID + j];
    __syncthreads();
    {
        float aq[4] = {0,0,0,0}, ak[4] = {0,0,0,0}, av[4] = {0,0,0,0};
        const float4* wq = (const float4*)(Wq + (size_t)j * HID);
        const float4* wk = (const float4*)(Wk + (size_t)j * HID);
        const float4* wv = (const float4*)(Wv + (size_t)j * HID);
        #pragma unroll 4
        for (int d4 = 0; d4 < 32; ++d4) {
            float4 q4 = wq[d4], k4 = wk[d4], v4 = wv[d4];
            #pragma unroll
            for (int s = 0; s < 4; ++s) {
                float c0 = cs[s][d4*4+0], c1 = cs[s][d4*4+1];
                float c2 = cs[s][d4*4+2], c3 = cs[s][d4*4+3];
                aq[s] += q4.x*c0 + q4.y*c1 + q4.z*c2 + q4.w*c3;
                ak[s] += k4.x*c0 + k4.y*c1 + k4.z*c2 + k4.w*c3;
                av[s] += v4.x*c0 + v4.y*c1 + v4.z*c2 + v4.w*c3;
            }
        }
        #pragma unroll
        for (int s = 0; s < 4; ++s) {
            qs[s][j] = aq[s] + bq[j];
            ks[s][j] = ak[s] + bk[j];
            vs[s][j] = av[s] + bv[j];
        }
    }
    __syncthreads();
    if (j < 16) {
        int s = j >> 2, s2 = j & 3;
        float d = 0.0f;
        for (int dd = 0; dd < HID; ++dd) d += qs[s][dd] * ks[s2][dd];
        am[s][s2] = d * (1.0f / (sqrtf(128.0f) + 1e-8f));
    }
    __syncthreads();
    if (j < 4) {
        float r[4];
        float mx = -1e30f;
        #pragma unroll
        for (int c = 0; c < 4; ++c) { r[c] = am[j][c]; mx = fmaxf(mx, r[c]); }
        float sum = 0.0f;
        #pragma unroll
        for (int c = 0; c < 4; ++c) { r[c] = expf(r[c] - mx); sum += r[c]; }
        #pragma unroll
        for (int c = 0; c < 4; ++c) r[c] /= sum;
        float sum2 = 0.0f;
        #pragma unroll
        for (int c = 0; c < 4; ++c) { r[c] += 1e-10f; sum2 += r[c]; }
        #pragma unroll
        for (int c = 0; c < 4; ++c) {
            r[c] /= sum2;
            am[j][c] = fminf(fmaxf(r[c], 1e-7f), 1.0f);
        }
    }
    __syncthreads();
    #pragma unroll
    for (int s = 0; s < 4; ++s) {
        float v = 0.0f;
        #pragma unroll
        for (int s2 = 0; s2 < 4; ++s2) v += am[s][s2] * vs[s2][j];
        cx[s][j] = v;
    }
    __syncthreads();
    {
        int w = j >> 5, lane = j & 31;
        float x0 = cx[w][lane], x1 = cx[w][lane+32], x2 = cx[w][lane+64], x3 = cx[w][lane+96];
        float s = x0 + x1 + x2 + x3;
        #pragma unroll
        for (int o = 16; o > 0; o >>= 1) s += __shfl_xor_sync(0xffffffffu, s, o);
        float mean = s * (1.0f / 128.0f);
        float d0 = x0 - mean, d1 = x1 - mean, d2 = x2 - mean, d3 = x3 - mean;
        float v = d0*d0 + d1*d1 + d2*d2 + d3*d3;
        #pragma unroll
        for (int o = 16; o > 0; o >>= 1) v += __shfl_xor_sync(0xffffffffu, v, o);
        float inv = rsqrtf(v * (1.0f / 128.0f) + 1e-5f);
        cx[w][lane]    = d0 * inv * g2[lane]    + b2[lane];
        cx[w][lane+32] = d1 * inv * g2[lane+32] + b2[lane+32];
        cx[w][lane+64] = d2 * inv * g2[lane+64] + b2[lane+64];
        cx[w][lane+96] = d3 * inv * g2[lane+96] + b2[lane+96];
    }
    __syncthreads();
    {
        const float4* wo = (const float4*)(Wo + (size_t)j * HID);
        float ao[4] = {0,0,0,0};
        #pragma unroll 4
        for (int d4 = 0; d4 < 32; ++d4) {
            float4 w4 = wo[d4];
            #pragma unroll
            for (int s = 0; s < 4; ++s) {
                ao[s] += w4.x * cx[s][d4*4+0] + w4.y * cx[s][d4*4+1]
                       + w4.z * cx[s][d4*4+2] + w4.w * cx[s][d4*4+3];
            }
        }
        #pragma unroll
        for (int s = 0; s < 4; ++s)
            SF[(size_t)(t*4 + s) * HID + j] = ao[s] + bo[j];
    }
}

// ---------------------------------------------------------------------------
// Cosine logits: one block per task
// ---------------------------------------------------------------------------
__global__ void __launch_bounds__(128) k_logits(
    const float* __restrict__ QF, const float* __restrict__ SF,
    float* __restrict__ out)
{
    __shared__ float pn[4][HID];
    int t = blockIdx.x;
    int w = threadIdx.x >> 5, lane = threadIdx.x & 31;
    {
        const float4* row = (const float4*)(SF + (size_t)(t*4 + w) * HID);
        float4 x = row[lane];
        float n2 = x.x*x.x + x.y*x.y + x.z*x.z + x.w*x.w;
        #pragma unroll
        for (int o = 16; o > 0; o >>= 1) n2 += __shfl_xor_sync(0xffffffffu, n2, o);
        float inv = 1.0f / fmaxf(sqrtf(n2), 1e-8f);
        float4 y;
        y.x = x.x * inv; y.y = x.y * inv; y.z = x.z * inv; y.w = x.w * inv;
        ((float4*)pn[w])[lane] = y;
    }
    __syncthreads();
    for (int q = w; q < 64; q += 4) {
        const float4* row = (const float4*)(QF + (size_t)(t*64 + q) * HID);
        float4 x = row[lane];
        float n2 = x.x*x.x + x.y*x.y + x.z*x.z + x.w*x.w;
        float d[4];
        #pragma unroll
        for (int c = 0; c < 4; ++c) {
            float4 p = ((const float4*)pn[c])[lane];
            d[c] = x.x*p.x + x.y*p.y + x.z*p.z + x.w*p.w;
        }
        #pragma unroll
        for (int o = 16; o > 0; o >>= 1) {
            n2 += __shfl_xor_sync(0xffffffffu, n2, o);
            #pragma unroll
            for (int c = 0; c < 4; ++c)
                d[c] += __shfl_xor_sync(0xffffffffu, d[c], o);
        }
        if (lane == 0) {
            float inv = 10.0f / fmaxf(sqrtf(n2), 1e-8f);
            float4 r;
            r.x = d[0]*inv; r.y = d[1]*inv; r.z = d[2]*inv; r.w = d[3]*inv;
            ((float4*)(out + ((size_t)t*64 + q) * 4))[0] = r;
        }
    }
}

extern "C" void kernel_launch(void* const* d_in, const int* in_sizes, int n_in,
                              void* d_out, int out_size)
{
    const float* s_img = (const float*)d_in[0];
    const float* s_txt = (const float*)d_in[1];
    /* d_in[2] = support_labels (unused) */
    const float* q_img = (const float*)d_in[3];
    const float* q_txt = (const float*)d_in[4];
    const float* Wi = (const float*)d_in[5];
    const float* bi = (const float*)d_in[6];
    const float* Wt = (const float*)d_in[7];
    const float* bt = (const float*)d_in[8];
    const float* g1 = (const float*)d_in[9];
    const float* b1 = (const float*)d_in[10];
    const float* Wq = (const float*)d_in[11];
    const float* bq = (const float*)d_in[12];
    const float* Wk = (const float*)d_in[13];
    const float* bk = (const float*)d_in[14];
    const float* Wv = (const float*)d_in[15];
    const float* bv = (const float*)d_in[16];
    const float* g2 = (const float*)d_in[17];
    const float* b2 = (const float*)d_in[18];
    const float* Wo = (const float*)d_in[19];
    const float* bo = (const float*)d_in[20];

    float *pC, *pQF, *pSF;
    cudaGetSymbolAddress((void**)&pC, g_C);
    cudaGetSymbolAddress((void**)&pQF, g_QF);
    cudaGetSymbolAddress((void**)&pSF, g_SF);
    __nv_bfloat16 *pWvhi, *pWvlo, *pWohi, *pWolo;
    cudaGetSymbolAddress((void**)&pWvhi, g_Wvhi);
    cudaGetSymbolAddress((void**)&pWvlo, g_Wvlo);
    cudaGetSymbolAddress((void**)&pWohi, g_Wohi);
    cudaGetSymbolAddress((void**)&pWolo, g_Wolo);

    const int SMEM_IN = 2048 + 3 * STAGE;       // 198656
    static bool attr_set = false;
    if (!attr_set) {
        cudaFuncSetAttribute(k_input_mega,
                             cudaFuncAttributeMaxDynamicSharedMemorySize, SMEM_IN);
        attr_set = true;
    }

    // 0) preconvert weights into bf16 hi/lo
    k_wconv<<<(HID * KTOT / 4 + 255) / 256, 256>>>(Wi, Wt);
    k_wconv_h<<<16, 256>>>(Wv, pWvhi, pWvlo);
    k_wconv_h<<<16, 256>>>(Wo, pWohi, pWolo);
    // 1) mega kernel: input projection + LN1 (+ full query chain for query blocks)
    k_input_mega<<<NTOK / 128, 512, SMEM_IN>>>(s_img, s_txt, q_img, q_txt,
                                               bi, bt, g1, b1, bv, g2, b2, bo);
    // 2) support path: tiny full attention per task
    k_support_attn<<<256, 128>>>(pC, Wq, bq, Wk, bk, Wv, bv, g2, b2, Wo, bo, pSF);
    // 3) cosine logits
    k_logits<<<256, 128>>>(pQF, pSF, (float*)d_out);
}

// round 13
// speedup vs baseline: 1.1376x; 1.0364x over previous
#include <cuda_runtime.h>
#include <cuda_bf16.h>
#include <math.h>
#include <stdint.h>

#define HID 128
#define DI 2048
#define DT 768
#define KTOT 2816
#define TSUP 1024
#define TQRY 16384
#define NTOK 17408
#define BK 64
#define NCH 44   /* 2816 / 64 */
#define STAGE 65536   /* per-stage: Ahi 16K, Alo 16K, Whi 16K, Wlo 16K */

// Scratch (static __device__ per allocation rules)
__device__ float g_C[NTOK * HID];     // LN1'd features (support blocks only)
__device__ float g_QF[TQRY * HID];
__device__ __nv_bfloat16 g_Whi[HID * KTOT];
__device__ __nv_bfloat16 g_Wlo[HID * KTOT];
__device__ __nv_bfloat16 g_Wvhi[HID * HID];
__device__ __nv_bfloat16 g_Wvlo[HID * HID];
__device__ __nv_bfloat16 g_Wohi[HID * HID];
__device__ __nv_bfloat16 g_Wolo[HID * HID];

// ---------------------------------------------------------------------------
// helpers
// ---------------------------------------------------------------------------
__device__ __forceinline__ uint32_t smem_u32_of(const void* p) {
    uint32_t a;
    asm("{ .reg .u64 t; cvta.to.shared.u64 t, %1; cvt.u32.u64 %0, t; }"
        : "=r"(a) : "l"(p));
    return a;
}
static __device__ __forceinline__ uint32_t sw128(uint32_t off) {
    return off ^ ((off >> 3) & 0x70);
}
__device__ __forceinline__ void ldsm4(uint32_t* r, uint32_t addr) {
    asm volatile("ldmatrix.sync.aligned.m8n8.x4.shared.b16 {%0,%1,%2,%3}, [%4];"
                 : "=r"(r[0]), "=r"(r[1]), "=r"(r[2]), "=r"(r[3]) : "r"(addr));
}
__device__ __forceinline__ void mma16816(float* c, const uint32_t* a, const uint32_t* b) {
    asm volatile(
        "mma.sync.aligned.m16n8k16.row.col.f32.bf16.bf16.f32 "
        "{%0,%1,%2,%3}, {%4,%5,%6,%7}, {%8,%9}, {%0,%1,%2,%3};"
        : "+f"(c[0]), "+f"(c[1]), "+f"(c[2]), "+f"(c[3])
        : "r"(a[0]), "r"(a[1]), "r"(a[2]), "r"(a[3]), "r"(b[0]), "r"(b[1]));
}
__device__ __forceinline__ void cp16(uint32_t dst, const void* src) {
    asm volatile("cp.async.cg.shared.global [%0], [%1], 16;"
                 :: "r"(dst), "l"(src) : "memory");
}
#define CP_COMMIT() asm volatile("cp.async.commit_group;" ::: "memory")
#define CP_WAIT0()  asm volatile("cp.async.wait_group 0;" ::: "memory")
#define CP_WAIT1()  asm volatile("cp.async.wait_group 1;" ::: "memory")

__device__ __forceinline__ void split2(float x, float y, uint32_t& hi, uint32_t& lo) {
    __nv_bfloat162 h = __float22bfloat162_rn(make_float2(x, y));
    float2 hf = __bfloat1622float2(h);
    __nv_bfloat162 l = __float22bfloat162_rn(make_float2(x - hf.x, y - hf.y));
    hi = *(uint32_t*)&h;
    lo = *(uint32_t*)&l;
}

// ---------------------------------------------------------------------------
// 16-warp fragment map + 32x32-tile bf16x3 compute over one 64-K chunk
// ---------------------------------------------------------------------------
struct Frag16 {
    uint32_t abase[2], aswz[2], bbase[2], bswz[2];
};
__device__ __forceinline__ void make_frag16(Frag16& fm, int lane, int mw, int nw) {
    #pragma unroll
    for (int mt = 0; mt < 2; ++mt) {
        uint32_t rb = (uint32_t)(mw * 32 + mt * 16 + (lane & 15)) * 128 + (lane >> 4) * 16;
        fm.abase[mt] = rb; fm.aswz[mt] = (rb >> 3) & 0x70;
    }
    #pragma unroll
    for (int p = 0; p < 2; ++p) {
        uint32_t rb = (uint32_t)(nw * 32 + p * 16 + ((lane >> 4) & 1) * 8 + (lane & 7)) * 128
                    + ((lane >> 3) & 1) * 16;
        fm.bbase[p] = rb; fm.bswz[p] = (rb >> 3) & 0x70;
    }
}
__device__ __forceinline__ void compute_c16(
    uint32_t AHI, uint32_t ALO, uint32_t WHI, uint32_t WLO,
    const Frag16& fm, float (*acc)[4][4])
{
    #pragma unroll
    for (int ks = 0; ks < 4; ++ks) {
        uint32_t ahi[2][4], alo[2][4];
        #pragma unroll
        for (int mt = 0; mt < 2; ++mt) {
            uint32_t o = (fm.abase[mt] + ks * 32) ^ fm.aswz[mt];
            ldsm4(ahi[mt], AHI + o);
            ldsm4(alo[mt], ALO + o);
        }
        uint32_t bhi[2][4], blo[2][4];
        #pragma unroll
        for (int p = 0; p < 2; ++p) {
            uint32_t o = (fm.bbase[p] + ks * 32) ^ fm.bswz[p];
            ldsm4(bhi[p], WHI + o);
            ldsm4(blo[p], WLO + o);
        }
        #pragma unroll
        for (int mt = 0; mt < 2; ++mt)
            #pragma unroll
            for (int j = 0; j < 4; ++j)
                mma16816(acc[mt][j], ahi[mt], &bhi[j >> 1][(j & 1) * 2]);
        #pragma unroll
        for (int mt = 0; mt < 2; ++mt)
            #pragma unroll
            for (int j = 0; j < 4; ++j)
                mma16816(acc[mt][j], ahi[mt], &blo[j >> 1][(j & 1) * 2]);
        #pragma unroll
        for (int mt = 0; mt < 2; ++mt)
            #pragma unroll
            for (int j = 0; j < 4; ++j)
                mma16816(acc[mt][j], alo[mt], &bhi[j >> 1][(j & 1) * 2]);
    }
}

// ---------------------------------------------------------------------------
// Single weight-preconvert kernel: blocks [0,352) main W, [352,368) Wv,
// [368,384) Wo.
// ---------------------------------------------------------------------------
__global__ void __launch_bounds__(256) k_wconv_all(
    const float* __restrict__ Wi, const float* __restrict__ Wt,
    const float* __restrict__ Wv, const float* __restrict__ Wo)
{
    int b = blockIdx.x;
    if (b < 352) {
        int f4 = b * 256 + threadIdx.x;
        if (f4 >= HID * KTOT / 4) return;
        int row = f4 / (KTOT / 4);
        int col = (f4 % (KTOT / 4)) * 4;
        float4 v;
        if (col < DI) v = *(const float4*)(Wi + (size_t)row * DI + col);
        else          v = *(const float4*)(Wt + (size_t)row * DT + (col - DI));
        uint2 uh, ul;
        split2(v.x, v.y, uh.x, ul.x);
        split2(v.z, v.w, uh.y, ul.y);
        *(uint2*)(g_Whi + (size_t)row * KTOT + col) = uh;
        *(uint2*)(g_Wlo + (size_t)row * KTOT + col) = ul;
    } else {
        const bool isV = (b < 368);
        int f4 = (b - (isV ? 352 : 368)) * 256 + threadIdx.x;
        const float* W = isV ? Wv : Wo;
        __nv_bfloat16* hi = isV ? g_Wvhi : g_Wohi;
        __nv_bfloat16* lo = isV ? g_Wvlo : g_Wolo;
        float4 v = *(const float4*)(W + (size_t)f4 * 4);
        uint2 uh, ul;
        split2(v.x, v.y, uh.x, ul.x);
        split2(v.z, v.w, uh.y, ul.y);
        *(uint2*)(hi + (size_t)f4 * 4) = uh;
        *(uint2*)(lo + (size_t)f4 * 4) = ul;
    }
}

// ---------------------------------------------------------------------------
// MEGA KERNEL (unchanged from round 12): input projection + LN1; query
// blocks continue through LN2/Wv/Wo to g_QF, support blocks write g_C.
// ---------------------------------------------------------------------------
__global__ void __launch_bounds__(512) k_input_mega(
    const float* __restrict__ s_img, const float* __restrict__ s_txt,
    const float* __restrict__ q_img, const float* __restrict__ q_txt,
    const float* __restrict__ bi, const float* __restrict__ bt,
    const float* __restrict__ g1, const float* __restrict__ b1,
    const float* __restrict__ bv, const float* __restrict__ g2,
    const float* __restrict__ b2, const float* __restrict__ bo)
{
    extern __shared__ char smem[];
    const uint32_t sb = smem_u32_of(smem);
    float* bsum = (float*)smem;
    const uint32_t BASE = sb + 2048;

    const int tid = threadIdx.x, lane = tid & 31, wid = tid >> 5;
    const int mw = wid & 3, nw = wid >> 2;
    const int tokbase = blockIdx.x * 128;
    const bool isQuery = (tokbase >= TSUP);

    const float* img; const float* txt;
    if (!isQuery) {
        img = s_img + (size_t)tokbase * DI;
        txt = s_txt + (size_t)tokbase * DT;
    } else {
        img = q_img + (size_t)(tokbase - TSUP) * DI;
        txt = q_txt + (size_t)(tokbase - TSUP) * DT;
    }
    if (tid < HID) bsum[tid] = bi[tid] + bt[tid];

    const int row = tid >> 2;
    const int cq  = (tid & 3) * 16;

    Frag16 fm;
    make_frag16(fm, lane, mw, nw);

    float acc[2][4][4];
    #pragma unroll
    for (int mt = 0; mt < 2; ++mt)
        #pragma unroll
        for (int j = 0; j < 4; ++j)
            #pragma unroll
            for (int q = 0; q < 4; ++q) acc[mt][j][q] = 0.0f;

    float4 areg[4];
    auto loadA = [&](int c) {
        int kg = c * BK;
        const float4* ap;
        if (kg < DI) ap = (const float4*)(img + (size_t)row * DI + kg + cq);
        else         ap = (const float4*)(txt + (size_t)row * DT + (kg - DI) + cq);
        #pragma unroll
        for (int i = 0; i < 4; ++i) areg[i] = ap[i];
    };
    auto storeA = [&](uint32_t buf) {
        char* pAhi = smem + (buf - sb);
        char* pAlo = pAhi + 16384;
        #pragma unroll
        for (int i = 0; i < 4; ++i) {
            float4 f = areg[i];
            uint2 uh, ul;
            split2(f.x, f.y, uh.x, ul.x);
            split2(f.z, f.w, uh.y, ul.y);
            uint32_t off = sw128((uint32_t)(row * 128 + (cq + i * 4) * 2));
            *(uint2*)(pAhi + off) = uh;
            *(uint2*)(pAlo + off) = ul;
        }
    };
    auto loadW = [&](int c, uint32_t buf) {
        int kg = c * BK;
        const __nv_bfloat16* sh = g_Whi + (size_t)row * KTOT + kg + cq;
        const __nv_bfloat16* sl = g_Wlo + (size_t)row * KTOT + kg + cq;
        #pragma unroll
        for (int i = 0; i < 2; ++i) {
            uint32_t off = sw128((uint32_t)(row * 128 + (cq + i * 8) * 2));
            cp16(buf + 32768 + off, sh + i * 8);
            cp16(buf + 49152 + off, sl + i * 8);
        }
    };

    loadA(0); storeA(BASE + 0 * STAGE); loadW(0, BASE + 0 * STAGE); CP_COMMIT();
    loadA(1); storeA(BASE + 1 * STAGE); loadW(1, BASE + 1 * STAGE); CP_COMMIT();
    loadA(2);

    for (int c = 0; c < NCH; ++c) {
        if (c + 1 < NCH) CP_WAIT1(); else CP_WAIT0();
        __syncthreads();
        if (c + 2 < NCH) {
            uint32_t nbuf = BASE + (uint32_t)((c + 2) % 3) * STAGE;
            storeA(nbuf);
            loadW(c + 2, nbuf);
            CP_COMMIT();
            if (c + 3 < NCH) loadA(c + 3);
        }
        uint32_t cur = BASE + (uint32_t)(c % 3) * STAGE;
        compute_c16(cur, cur + 16384, cur + 32768, cur + 49152, fm, acc);
    }

    __syncthreads();
    float* Vs = (float*)(smem + 2048);
    const uint32_t CN = BASE + 1 * STAGE;
    const uint32_t WT = BASE + 2 * STAGE;

    const int schunk = (tid >> 1) & 1;
    const int sch = (tid & 1) * 32;
    auto loadWpair = [&](const __nv_bfloat16* hi, const __nv_bfloat16* lo, uint32_t dst) {
        const __nv_bfloat16* h = hi + (size_t)row * HID + schunk * BK + sch;
        const __nv_bfloat16* l = lo + (size_t)row * HID + schunk * BK + sch;
        #pragma unroll
        for (int i = 0; i < 4; ++i) {
            uint32_t off = sw128((uint32_t)(row * 128 + (sch + i * 8) * 2));
            cp16(dst + schunk * 32768 + off, h + i * 8);
            cp16(dst + schunk * 32768 + 16384 + off, l + i * 8);
        }
    };
    if (isQuery) { loadWpair(g_Wvhi, g_Wvlo, WT); CP_COMMIT(); }

    {
        const int g = lane >> 2, t = lane & 3;
        #pragma unroll
        for (int mt = 0; mt < 2; ++mt) {
            int r0 = mw * 32 + mt * 16 + g;
            #pragma unroll
            for (int j = 0; j < 4; ++j) {
                int col = nw * 32 + j * 8 + t * 2;
                float b0 = bsum[col], b1v = bsum[col + 1];
                *(float2*)&Vs[r0 * 128 + col] =
                    make_float2(acc[mt][j][0] + b0, acc[mt][j][1] + b1v);
                *(float2*)&Vs[(r0 + 8) * 128 + col] =
                    make_float2(acc[mt][j][2] + b0, acc[mt][j][3] + b1v);
            }
        }
    }
    __syncthreads();

    const int cch = lane >> 4;
    const int lc  = (lane * 4) & 63;
    {
        float4 gg = ((const float4*)g1)[lane];
        float4 bb = ((const float4*)b1)[lane];
        char* pNhi = smem + 2048 + STAGE + cch * 32768;
        char* pNlo = pNhi + 16384;
        for (int tt = wid * 8; tt < wid * 8 + 8; ++tt) {
            float4 x = ((const float4*)&Vs[tt * 128])[lane];
            float s = x.x + x.y + x.z + x.w;
            #pragma unroll
            for (int o = 16; o > 0; o >>= 1) s += __shfl_xor_sync(0xffffffffu, s, o);
            float mean = s * (1.0f / 128.0f);
            float d0 = x.x - mean, d1 = x.y - mean, d2 = x.z - mean, d3 = x.w - mean;
            float v = d0*d0 + d1*d1 + d2*d2 + d3*d3;
            #pragma unroll
            for (int o = 16; o > 0; o >>= 1) v += __shfl_xor_sync(0xffffffffu, v, o);
            float inv = rsqrtf(v * (1.0f / 128.0f) + 1e-5f);
            float y0 = d0 * inv * gg.x + bb.x;
            float y1 = d1 * inv * gg.y + bb.y;
            float y2 = d2 * inv * gg.z + bb.z;
            float y3 = d3 * inv * gg.w + bb.w;
            if (!isQuery) {
                float4 y = make_float4(y0, y1, y2, y3);
                ((float4*)&g_C[(size_t)(tokbase + tt) * HID])[lane] = y;
            } else {
                uint2 uh, ul;
                split2(y0, y1, uh.x, ul.x);
                split2(y2, y3, uh.y, ul.y);
                uint32_t off = sw128((uint32_t)(tt * 128 + lc * 2));
                *(uint2*)(pNhi + off) = uh;
                *(uint2*)(pNlo + off) = ul;
            }
        }
    }
    if (!isQuery) return;

    CP_WAIT0();
    __syncthreads();

    #pragma unroll
    for (int mt = 0; mt < 2; ++mt)
        #pragma unroll
        for (int j = 0; j < 4; ++j)
            #pragma unroll
            for (int q = 0; q < 4; ++q) acc[mt][j][q] = 0.0f;
    #pragma unroll
    for (int c = 0; c < 2; ++c)
        compute_c16(CN + c * 32768, CN + c * 32768 + 16384,
                    WT + c * 32768, WT + c * 32768 + 16384, fm, acc);
    __syncthreads();

    loadWpair(g_Wohi, g_Wolo, CN);
    CP_COMMIT();

    {
        const int g = lane >> 2, t = lane & 3;
        #pragma unroll
        for (int mt = 0; mt < 2; ++mt) {
            int r0 = mw * 32 + mt * 16 + g;
            #pragma unroll
            for (int j = 0; j < 4; ++j) {
                int col = nw * 32 + j * 8 + t * 2;
                float b0 = bv[col], b1v = bv[col + 1];
                *(float2*)&Vs[r0 * 128 + col] =
                    make_float2(acc[mt][j][0] + b0, acc[mt][j][1] + b1v);
                *(float2*)&Vs[(r0 + 8) * 128 + col] =
                    make_float2(acc[mt][j][2] + b0, acc[mt][j][3] + b1v);
            }
        }
    }
    __syncthreads();

    {
        float4 gg = ((const float4*)g2)[lane];
        float4 bb = ((const float4*)b2)[lane];
        char* pNhi = smem + 2048 + 2 * STAGE + cch * 32768;
        char* pNlo = pNhi + 16384;
        for (int tt = wid * 8; tt < wid * 8 + 8; ++tt) {
            float4 x = ((const float4*)&Vs[tt * 128])[lane];
            float s = x.x + x.y + x.z + x.w;
            #pragma unroll
            for (int o = 16; o > 0; o >>= 1) s += __shfl_xor_sync(0xffffffffu, s, o);
            float mean = s * (1.0f / 128.0f);
            float d0 = x.x - mean, d1 = x.y - mean, d2 = x.z - mean, d3 = x.w - mean;
            float v = d0*d0 + d1*d1 + d2*d2 + d3*d3;
            #pragma unroll
            for (int o = 16; o > 0; o >>= 1) v += __shfl_xor_sync(0xffffffffu, v, o);
            float inv = rsqrtf(v * (1.0f / 128.0f) + 1e-5f);
            float y0 = d0 * inv * gg.x + bb.x;
            float y1 = d1 * inv * gg.y + bb.y;
            float y2 = d2 * inv * gg.z + bb.z;
            float y3 = d3 * inv * gg.w + bb.w;
            uint2 uh, ul;
            split2(y0, y1, uh.x, ul.x);
            split2(y2, y3, uh.y, ul.y);
            uint32_t off = sw128((uint32_t)(tt * 128 + lc * 2));
            *(uint2*)(pNhi + off) = uh;
            *(uint2*)(pNlo + off) = ul;
        }
    }
    CP_WAIT0();
    __syncthreads();

    #pragma unroll
    for (int mt = 0; mt < 2; ++mt)
        #pragma unroll
        for (int j = 0; j < 4; ++j)
            #pragma unroll
            for (int q = 0; q < 4; ++q) acc[mt][j][q] = 0.0f;
    #pragma unroll
    for (int c = 0; c < 2; ++c)
        compute_c16(WT + c * 32768, WT + c * 32768 + 16384,
                    CN + c * 32768, CN + c * 32768 + 16384, fm, acc);

    {
        const int g = lane >> 2, t = lane & 3;
        const int qbase = tokbase - TSUP;
        #pragma unroll
        for (int mt = 0; mt < 2; ++mt) {
            int r0 = qbase + mw * 32 + mt * 16 + g;
            #pragma unroll
            for (int j = 0; j < 4; ++j) {
                int col = nw * 32 + j * 8 + t * 2;
                float b0 = bo[col], b1v = bo[col + 1];
                *(float2*)&g_QF[(size_t)r0 * HID + col] =
                    make_float2(acc[mt][j][0] + b0, acc[mt][j][1] + b1v);
                *(float2*)&g_QF[(size_t)(r0 + 8) * HID + col] =
                    make_float2(acc[mt][j][2] + b0, acc[mt][j][3] + b1v);
            }
        }
    }
}

// ---------------------------------------------------------------------------
// Fused tail: per task t — support attention (4 tokens) -> SF rows in smem,
// normalize, then cosine logits against that task's 64 QF rows.
// ---------------------------------------------------------------------------
__global__ void __launch_bounds__(128) k_tail(
    const float* __restrict__ C,
    const float* __restrict__ Wq, const float* __restrict__ bq,
    const float* __restrict__ Wk, const float* __restrict__ bk,
    const float* __restrict__ Wv, const float* __restrict__ bv,
    const float* __restrict__ g2, const float* __restrict__ b2,
    const float* __restrict__ Wo, const float* __restrict__ bo,
    const float* __restrict__ QF, float* __restrict__ out)
{
    __shared__ float cs[4][HID], qs[4][HID], ks_[4][HID], vs[4][HID];
    __shared__ float am[4][4];
    __shared__ float cx[4][HID];
    __shared__ float pn[4][HID];
    int t = blockIdx.x;
    int j = threadIdx.x;
    const float* base = C + (size_t)t * 4 * HID;
    #pragma unroll
    for (int s = 0; s < 4; ++s) cs[s][j] = base[s * HID + j];
    __syncthreads();
    {
        float aq[4] = {0,0,0,0}, ak[4] = {0,0,0,0}, av[4] = {0,0,0,0};
        const float4* wq = (const float4*)(Wq + (size_t)j * HID);
        const float4* wk = (const float4*)(Wk + (size_t)j * HID);
        const float4* wv = (const float4*)(Wv + (size_t)j * HID);
        #pragma unroll 4
        for (int d4 = 0; d4 < 32; ++d4) {
            float4 q4 = wq[d4], k4 = wk[d4], v4 = wv[d4];
            #pragma unroll
            for (int s = 0; s < 4; ++s) {
                float c0 = cs[s][d4*4+0], c1 = cs[s][d4*4+1];
                float c2 = cs[s][d4*4+2], c3 = cs[s][d4*4+3];
                aq[s] += q4.x*c0 + q4.y*c1 + q4.z*c2 + q4.w*c3;
                ak[s] += k4.x*c0 + k4.y*c1 + k4.z*c2 + k4.w*c3;
                av[s] += v4.x*c0 + v4.y*c1 + v4.z*c2 + v4.w*c3;
            }
        }
        #pragma unroll
        for (int s = 0; s < 4; ++s) {
            qs[s][j]  = aq[s] + bq[j];
            ks_[s][j] = ak[s] + bk[j];
            vs[s][j]  = av[s] + bv[j];
        }
    }
    __syncthreads();
    if (j < 16) {
        int s = j >> 2, s2 = j & 3;
        float d = 0.0f;
        for (int dd = 0; dd < HID; ++dd) d += qs[s][dd] * ks_[s2][dd];
        am[s][s2] = d * (1.0f / (sqrtf(128.0f) + 1e-8f));
    }
    __syncthreads();
    if (j < 4) {
        float r[4];
        float mx = -1e30f;
        #pragma unroll
        for (int c = 0; c < 4; ++c) { r[c] = am[j][c]; mx = fmaxf(mx, r[c]); }
        float sum = 0.0f;
        #pragma unroll
        for (int c = 0; c < 4; ++c) { r[c] = expf(r[c] - mx); sum += r[c]; }
        #pragma unroll
        for (int c = 0; c < 4; ++c) r[c] /= sum;
        float sum2 = 0.0f;
        #pragma unroll
        for (int c = 0; c < 4; ++c) { r[c] += 1e-10f; sum2 += r[c]; }
        #pragma unroll
        for (int c = 0; c < 4; ++c) {
            r[c] /= sum2;
            am[j][c] = fminf(fmaxf(r[c], 1e-7f), 1.0f);
        }
    }
    __syncthreads();
    #pragma unroll
    for (int s = 0; s < 4; ++s) {
        float v = 0.0f;
        #pragma unroll
        for (int s2 = 0; s2 < 4; ++s2) v += am[s][s2] * vs[s2][j];
        cx[s][j] = v;
    }
    __syncthreads();
    {
        int w = j >> 5, lane = j & 31;
        float x0 = cx[w][lane], x1 = cx[w][lane+32], x2 = cx[w][lane+64], x3 = cx[w][lane+96];
        float s = x0 + x1 + x2 + x3;
        #pragma unroll
        for (int o = 16; o > 0; o >>= 1) s += __shfl_xor_sync(0xffffffffu, s, o);
        float mean = s * (1.0f / 128.0f);
        float d0 = x0 - mean, d1 = x1 - mean, d2 = x2 - mean, d3 = x3 - mean;
        float v = d0*d0 + d1*d1 + d2*d2 + d3*d3;
        #pragma unroll
        for (int o = 16; o > 0; o >>= 1) v += __shfl_xor_sync(0xffffffffu, v, o);
        float inv = rsqrtf(v * (1.0f / 128.0f) + 1e-5f);
        cx[w][lane]    = d0 * inv * g2[lane]    + b2[lane];
        cx[w][lane+32] = d1 * inv * g2[lane+32] + b2[lane+32];
        cx[w][lane+64] = d2 * inv * g2[lane+64] + b2[lane+64];
        cx[w][lane+96] = d3 * inv * g2[lane+96] + b2[lane+96];
    }
    __syncthreads();
    {
        const float4* wo = (const float4*)(Wo + (size_t)j * HID);
        float ao[4] = {0,0,0,0};
        #pragma unroll 4
        for (int d4 = 0; d4 < 32; ++d4) {
            float4 w4 = wo[d4];
            #pragma unroll
            for (int s = 0; s < 4; ++s) {
                ao[s] += w4.x * cx[s][d4*4+0] + w4.y * cx[s][d4*4+1]
                       + w4.z * cx[s][d4*4+2] + w4.w * cx[s][d4*4+3];
            }
        }
        #pragma unroll
        for (int s = 0; s < 4; ++s)
            qs[s][j] = ao[s] + bo[j];   // SF rows (reuse qs)
    }
    __syncthreads();

    // normalize SF rows -> pn
    int w = j >> 5, lane = j & 31;
    {
        float4 x = ((const float4*)qs[w])[lane];
        float n2 = x.x*x.x + x.y*x.y + x.z*x.z + x.w*x.w;
        #pragma unroll
        for (int o = 16; o > 0; o >>= 1) n2 += __shfl_xor_sync(0xffffffffu, n2, o);
        float inv = 1.0f / fmaxf(sqrtf(n2), 1e-8f);
        float4 y;
        y.x = x.x * inv; y.y = x.y * inv; y.z = x.z * inv; y.w = x.w * inv;
        ((float4*)pn[w])[lane] = y;
    }
    __syncthreads();

    // cosine logits against this task's 64 QF rows
    for (int q = w; q < 64; q += 4) {
        const float4* row = (const float4*)(QF + (size_t)(t*64 + q) * HID);
        float4 x = row[lane];
        float n2 = x.x*x.x + x.y*x.y + x.z*x.z + x.w*x.w;
        float d[4];
        #pragma unroll
        for (int c = 0; c < 4; ++c) {
            float4 p = ((const float4*)pn[c])[lane];
            d[c] = x.x*p.x + x.y*p.y + x.z*p.z + x.w*p.w;
        }
        #pragma unroll
        for (int o = 16; o > 0; o >>= 1) {
            n2 += __shfl_xor_sync(0xffffffffu, n2, o);
            #pragma unroll
            for (int c = 0; c < 4; ++c)
                d[c] += __shfl_xor_sync(0xffffffffu, d[c], o);
        }
        if (lane == 0) {
            float inv = 10.0f / fmaxf(sqrtf(n2), 1e-8f);
            float4 r;
            r.x = d[0]*inv; r.y = d[1]*inv; r.z = d[2]*inv; r.w = d[3]*inv;
            ((float4*)(out + ((size_t)t*64 + q) * 4))[0] = r;
        }
    }
}

extern "C" void kernel_launch(void* const* d_in, const int* in_sizes, int n_in,
                              void* d_out, int out_size)
{
    const float* s_img = (const float*)d_in[0];
    const float* s_txt = (const float*)d_in[1];
    /* d_in[2] = support_labels (unused) */
    const float* q_img = (const float*)d_in[3];
    const float* q_txt = (const float*)d_in[4];
    const float* Wi = (const float*)d_in[5];
    const float* bi = (const float*)d_in[6];
    const float* Wt = (const float*)d_in[7];
    const float* bt = (const float*)d_in[8];
    const float* g1 = (const float*)d_in[9];
    const float* b1 = (const float*)d_in[10];
    const float* Wq = (const float*)d_in[11];
    const float* bq = (const float*)d_in[12];
    const float* Wk = (const float*)d_in[13];
    const float* bk = (const float*)d_in[14];
    const float* Wv = (const float*)d_in[15];
    const float* bv = (const float*)d_in[16];
    const float* g2 = (const float*)d_in[17];
    const float* b2 = (const float*)d_in[18];
    const float* Wo = (const float*)d_in[19];
    const float* bo = (const float*)d_in[20];

    float *pC, *pQF;
    cudaGetSymbolAddress((void**)&pC, g_C);
    cudaGetSymbolAddress((void**)&pQF, g_QF);

    const int SMEM_IN = 2048 + 3 * STAGE;       // 198656
    static bool attr_set = false;
    if (!attr_set) {
        cudaFuncSetAttribute(k_input_mega,
                             cudaFuncAttributeMaxDynamicSharedMemorySize, SMEM_IN);
        attr_set = true;
    }

    // 1) single weight-preconvert launch
    k_wconv_all<<<384, 256>>>(Wi, Wt, Wv, Wo);
    // 2) mega kernel: input projection + LN1 (+ full query chain for query blocks)
    k_input_mega<<<NTOK / 128, 512, SMEM_IN>>>(s_img, s_txt, q_img, q_txt,
                                               bi, bt, g1, b1, bv, g2, b2, bo);
    // 3) fused tail: support attention + cosine logits, one block per task
    k_tail<<<256, 128>>>(pC, Wq, bq, Wk, bk, Wv, bv, g2, b2, Wo, bo,
                         pQF, (float*)d_out);
}